// round 14
// baseline (speedup 1.0000x reference)
#include <cuda_runtime.h>
#include <cuda_fp16.h>
#include <math.h>

#define G      2          // graphs per block
#define NODES  40         // G*20
#define NPG    20
#define HID    128
#define INDIM  9
#define KNN    5
#define ABS    136        // fp16 plane stride (halfs)
#define XAS    40         // fp16 xagg stride (halfs)

typedef unsigned int u32;

// Fused layer-1 weight: Wfused = We@W1 (9x128), bfused = 5*be@W1 + b1
__device__ float g_Wfused[INDIM * HID];
__device__ float g_bfused[HID];

// mma A-operand fragments, fp16 hi/lo planes.
__device__ u32 g_Wf1Hi[1024];
__device__ u32 g_Wf1Lo[1024];
__device__ u32 g_Wf2Hi[8192];
__device__ u32 g_Wf2Lo[8192];

__global__ void prep_fuse(const float* __restrict__ w_embed,
                          const float* __restrict__ b_embed,
                          const float* __restrict__ w1,
                          const float* __restrict__ b1) {
    int c = blockIdx.x * blockDim.x + threadIdx.x;
    if (c >= HID) return;
    #pragma unroll 1
    for (int j = 0; j < INDIM; ++j) {
        float s = 0.0f;
        for (int k = 0; k < HID; ++k)
            s = fmaf(w_embed[j * HID + k], w1[k * HID + c], s);
        g_Wfused[j * HID + c] = s;
    }
    float sb = 0.0f;
    for (int k = 0; k < HID; ++k)
        sb = fmaf(b_embed[k], w1[k * HID + c], sb);
    g_bfused[c] = 5.0f * sb + b1[c];
}

__global__ void prep_wfrag1() {
    int t = blockIdx.x * blockDim.x + threadIdx.x;   // 0..255
    if (t >= 256) return;
    int mt = t >> 5, l = t & 31;
    int gr = l >> 2, tig = l & 3;
    int base = (mt * 32 + l) * 4;
    #pragma unroll
    for (int r = 0; r < 4; ++r) {
        int row = gr + ((r & 1) ? 8 : 0);
        int kb  = tig * 2 + ((r >= 2) ? 8 : 0);
        int m = mt * 16 + row, k = kb;
        float v0 = (k     < INDIM) ? g_Wfused[k * HID + m]       : 0.0f;
        float v1 = (k + 1 < INDIM) ? g_Wfused[(k + 1) * HID + m] : 0.0f;
        __half h0 = __float2half(v0), h1 = __float2half(v1);
        float l0 = v0 - __half2float(h0), l1 = v1 - __half2float(h1);
        __half2 hi; hi.x = h0; hi.y = h1;
        __half2 lo; lo.x = __float2half(l0); lo.y = __float2half(l1);
        g_Wf1Hi[base + r] = *(u32*)&hi;
        g_Wf1Lo[base + r] = *(u32*)&lo;
    }
}

__global__ void prep_wfrag2(const float* __restrict__ w2) {
    int t = blockIdx.x * blockDim.x + threadIdx.x;   // 0..2047
    if (t >= 2048) return;
    int mt = t >> 8, kt = (t >> 5) & 7, l = t & 31;
    int gr = l >> 2, tig = l & 3;
    int base = ((mt * 8 + kt) * 32 + l) * 4;
    #pragma unroll
    for (int r = 0; r < 4; ++r) {
        int row = gr + ((r & 1) ? 8 : 0);
        int kb  = tig * 2 + ((r >= 2) ? 8 : 0);
        int m = mt * 16 + row, k = kt * 16 + kb;
        float v0 = w2[k * HID + m], v1 = w2[(k + 1) * HID + m];
        __half h0 = __float2half(v0), h1 = __float2half(v1);
        float l0 = v0 - __half2float(h0), l1 = v1 - __half2float(h1);
        __half2 hi; hi.x = h0; hi.y = h1;
        __half2 lo; lo.x = __float2half(l0); lo.y = __float2half(l1);
        g_Wf2Hi[base + r] = *(u32*)&hi;
        g_Wf2Lo[base + r] = *(u32*)&lo;
    }
}

__device__ __forceinline__ float gelu_exact(float x) {
    return 0.5f * x * (1.0f + erff(x * 0.70710678118654752440f));
}

#define MMA(d, a, b0v, b1v)                                                       \
    asm volatile("mma.sync.aligned.m16n8k16.row.col.f32.f16.f16.f32 "              \
                 "{%0,%1,%2,%3},{%4,%5,%6,%7},{%8,%9},{%0,%1,%2,%3};"              \
                 : "+f"(d[0]), "+f"(d[1]), "+f"(d[2]), "+f"(d[3])                  \
                 : "r"(a[0]), "r"(a[1]), "r"(a[2]), "r"(a[3]), "r"(b0v), "r"(b1v))

// Layer-1 fused GEMM: K=16 (9 real), X = xagg hi/lo planes, 3 mma terms.
__device__ __forceinline__ void gemm1p(const __half* __restrict__ XsHi,
                                       const __half* __restrict__ XsLo,
                                       int mgroup, int lane,
                                       float acc[2][5][4]) {
    const int gr = lane >> 2, tig = lane & 3;
    u32 ah[2][4], al[2][4];
    #pragma unroll
    for (int mt = 0; mt < 2; ++mt) {
        int idx = ((mgroup * 2 + mt) * 32 + lane) * 4;
        uint4 h = *(const uint4*)&g_Wf1Hi[idx];
        ah[mt][0] = h.x; ah[mt][1] = h.y; ah[mt][2] = h.z; ah[mt][3] = h.w;
        uint4 lo = *(const uint4*)&g_Wf1Lo[idx];
        al[mt][0] = lo.x; al[mt][1] = lo.y; al[mt][2] = lo.z; al[mt][3] = lo.w;
    }
    #pragma unroll
    for (int mt = 0; mt < 2; ++mt)
        #pragma unroll
        for (int nt = 0; nt < 5; ++nt)
            #pragma unroll
            for (int r = 0; r < 4; ++r) acc[mt][nt][r] = 0.0f;
    #pragma unroll
    for (int nt = 0; nt < 5; ++nt) {
        int n0 = nt * 8 + gr;
        u32 bh0 = *(const u32*)(XsHi + n0 * XAS + 2 * tig);
        u32 bh1 = *(const u32*)(XsHi + n0 * XAS + 2 * tig + 8);
        u32 bl0 = *(const u32*)(XsLo + n0 * XAS + 2 * tig);
        u32 bl1 = *(const u32*)(XsLo + n0 * XAS + 2 * tig + 8);
        #pragma unroll
        for (int mt = 0; mt < 2; ++mt) {
            MMA(acc[mt][nt], ah[mt], bh0, bh1);
            MMA(acc[mt][nt], al[mt], bh0, bh1);
            MMA(acc[mt][nt], ah[mt], bl0, bl1);
        }
    }
}

// Layer-2 GEMM: W2 = Wh+Wl fp16 planes vs single fp16 activation plane.
__device__ __forceinline__ void gemm2(const __half* __restrict__ Xs,
                                      int mgroup, int lane,
                                      float acc[2][5][4]) {
    const int gr = lane >> 2, tig = lane & 3;
    #pragma unroll
    for (int mt = 0; mt < 2; ++mt)
        #pragma unroll
        for (int nt = 0; nt < 5; ++nt)
            #pragma unroll
            for (int r = 0; r < 4; ++r) acc[mt][nt][r] = 0.0f;
    #pragma unroll
    for (int kt = 0; kt < 8; ++kt) {
        u32 ah[2][4], al[2][4];
        #pragma unroll
        for (int mt = 0; mt < 2; ++mt) {
            int idx = (((mgroup * 2 + mt) * 8 + kt) * 32 + lane) * 4;
            uint4 h = *(const uint4*)&g_Wf2Hi[idx];
            ah[mt][0] = h.x; ah[mt][1] = h.y; ah[mt][2] = h.z; ah[mt][3] = h.w;
            uint4 lo = *(const uint4*)&g_Wf2Lo[idx];
            al[mt][0] = lo.x; al[mt][1] = lo.y; al[mt][2] = lo.z; al[mt][3] = lo.w;
        }
        u32 bh[5][2];
        const int kb = kt * 16 + 2 * tig;
        #pragma unroll
        for (int nt = 0; nt < 5; ++nt) {
            int n0 = nt * 8 + gr;
            bh[nt][0] = *(const u32*)(Xs + n0 * ABS + kb);
            bh[nt][1] = *(const u32*)(Xs + n0 * ABS + kb + 8);
        }
        #pragma unroll
        for (int mt = 0; mt < 2; ++mt)
            #pragma unroll
            for (int nt = 0; nt < 5; ++nt) {
                MMA(acc[mt][nt], ah[mt], bh[nt][0], bh[nt][1]);
                MMA(acc[mt][nt], al[mt], bh[nt][0], bh[nt][1]);
            }
    }
}

// Shared LN stats: partials -> smem -> combine. All 128 threads participate.
__device__ __forceinline__ void ln_stats(float acc[2][5][4],
                                         const float bA[2], const float bB[2],
                                         float* pSum, float* pSq,
                                         float* meanv, float* rstdv,
                                         int mgroup, int lane) {
    const int gr = lane >> 2, tig = lane & 3;
    #pragma unroll
    for (int nt = 0; nt < 5; ++nt) {
        float sA = 0, sB = 0, qA = 0, qB = 0;
        #pragma unroll
        for (int mt = 0; mt < 2; ++mt) {
            float x0 = acc[mt][nt][0] + bA[mt];
            float x1 = acc[mt][nt][1] + bA[mt];
            float x2 = acc[mt][nt][2] + bB[mt];
            float x3 = acc[mt][nt][3] + bB[mt];
            sA += x0 + x2; sB += x1 + x3;
            qA += x0 * x0 + x2 * x2; qB += x1 * x1 + x3 * x3;
        }
        #pragma unroll
        for (int off = 4; off <= 16; off <<= 1) {
            sA += __shfl_xor_sync(0xffffffffu, sA, off);
            sB += __shfl_xor_sync(0xffffffffu, sB, off);
            qA += __shfl_xor_sync(0xffffffffu, qA, off);
            qB += __shfl_xor_sync(0xffffffffu, qB, off);
        }
        if (gr == 0) {
            int nA = nt * 8 + 2 * tig;
            pSum[mgroup * NODES + nA]     = sA;
            pSum[mgroup * NODES + nA + 1] = sB;
            pSq [mgroup * NODES + nA]     = qA;
            pSq [mgroup * NODES + nA + 1] = qB;
        }
    }
    __syncthreads();
    if (threadIdx.x < NODES) {
        int n = threadIdx.x;
        float S = pSum[n] + pSum[NODES + n] + pSum[2 * NODES + n] + pSum[3 * NODES + n];
        float Q = pSq[n]  + pSq[NODES + n]  + pSq[2 * NODES + n]  + pSq[3 * NODES + n];
        float m = S * (1.0f / 128.0f);
        float var = fmaxf(Q * (1.0f / 128.0f) - m * m, 0.0f);
        meanv[n] = m;
        rstdv[n] = rsqrtf(var + 1e-5f);
    }
    __syncthreads();
}

// agg over knn from fp16 h1h plane (LDS.128, HADD2), write fp16 Xs plane.
__device__ __forceinline__ void agg_h(const __half* __restrict__ h1h,
                                      const int* __restrict__ nbr,
                                      __half* __restrict__ Xs, int t) {
    #pragma unroll
    for (int i = 0; i < 5; ++i) {
        int q = t + 128 * i;              // 640 chunks of 8 halfs
        int n = q >> 4;
        int f8 = (q & 15) * 8;
        const int* nb = &nbr[n * KNN];
        uint4 a0 = *(const uint4*)(h1h + nb[0] * ABS + f8);
        __half2 s0 = *(__half2*)&a0.x, s1 = *(__half2*)&a0.y;
        __half2 s2 = *(__half2*)&a0.z, s3 = *(__half2*)&a0.w;
        #pragma unroll
        for (int r = 1; r < KNN; ++r) {
            uint4 a = *(const uint4*)(h1h + nb[r] * ABS + f8);
            s0 = __hadd2(s0, *(__half2*)&a.x);
            s1 = __hadd2(s1, *(__half2*)&a.y);
            s2 = __hadd2(s2, *(__half2*)&a.z);
            s3 = __hadd2(s3, *(__half2*)&a.w);
        }
        uint4 o;
        o.x = *(u32*)&s0; o.y = *(u32*)&s1; o.z = *(u32*)&s2; o.w = *(u32*)&s3;
        *(uint4*)(Xs + n * ABS + f8) = o;
    }
}

#define SMEM_BYTES 24160

__global__ __launch_bounds__(128, 4)
void hbond_gnn_mma(const float* __restrict__ x_all,
                   const float* __restrict__ g1,
                   const float* __restrict__ be1,
                   const float* __restrict__ b2,
                   const float* __restrict__ g2,
                   const float* __restrict__ be2,
                   float* __restrict__ out) {
    extern __shared__ char smem[];
    // Lifetimes: xs (load..xagg) aliases Xs (agg2..gemm2).
    //            XsHi/XsLo (xagg..gemm1p) alias h1h (epilogue1..end).
    __half* Xs   = (__half*)smem;                       // 40*136*2 = 10880
    float*  xs   = (float*)smem;                        // 360*4 = 1440 (alias)
    __half* h1h  = (__half*)(smem + 10880);             // 10880
    __half* XsHi = (__half*)(smem + 10880);             // 3200 (alias)
    __half* XsLo = (__half*)(smem + 14080);             // 3200 (alias)
    int*   nbr   = (int*)(smem + 21760);                // 200*4 = 800
    float* pSum  = (float*)(smem + 22560);              // 640
    float* pSq   = (float*)(smem + 23200);              // 640
    float* meanv = (float*)(smem + 23840);              // 160
    float* rstdv = (float*)(smem + 24000);              // 160

    const int t = threadIdx.x;
    const int lane = t & 31;
    const int mgroup = t >> 5;                           // warp = m-group (0..3)
    const int gr = lane >> 2, tig = lane & 3;
    const float* x = x_all + (size_t)blockIdx.x * (NODES * INDIM);

    // ---- node features ----
    for (int i = t; i < NODES * INDIM; i += 128) xs[i] = x[i];
    __syncthreads();

    // ---- KNN (d2 in registers; ties -> lower index) + exact fp32 xagg ----
    if (t < NODES) {
        const int gb = (t / NPG) * NPG;
        const float* pi = &xs[t * INDIM + 6];
        const float px = pi[0], py = pi[1], pz = pi[2];
        float d2r[NPG];
        #pragma unroll
        for (int j = 0; j < NPG; ++j) {
            const float* pj = &xs[(gb + j) * INDIM + 6];
            float dx = px - pj[0], dy = py - pj[1], dz = pz - pj[2];
            d2r[j] = fmaf(dx, dx, fmaf(dy, dy, dz * dz));
        }
        unsigned mask = 0;
        int nb[KNN];
        #pragma unroll
        for (int r = 0; r < KNN; ++r) {
            float best = 3.4e38f; int bj = 0;
            #pragma unroll
            for (int j = 0; j < NPG; ++j) {
                if (!((mask >> j) & 1u) && d2r[j] < best) { best = d2r[j]; bj = j; }
            }
            mask |= 1u << bj;
            nb[r] = gb + bj;
            nbr[t * KNN + r] = nb[r];
        }
        __half* hi = XsHi + t * XAS;
        __half* lo = XsLo + t * XAS;
        #pragma unroll
        for (int j = 0; j < INDIM; ++j) {
            float s = 0.0f;
            #pragma unroll
            for (int r = 0; r < KNN; ++r) s += xs[nb[r] * INDIM + j];
            __half h = __float2half(s);
            hi[j] = h;
            lo[j] = __float2half(s - __half2float(h));
        }
        const __half z = __float2half(0.0f);
        #pragma unroll
        for (int j = INDIM; j < 16; ++j) { hi[j] = z; lo[j] = z; }
    }
    __syncthreads();

    float acc[2][5][4];
    float bA[2], bB[2];

    // ==== fused layer 1: (adj@x)@(We@W1) + bfused -> LN1 -> gelu -> h1h (fp16) ====
    gemm1p(XsHi, XsLo, mgroup, lane, acc);
    #pragma unroll
    for (int mt = 0; mt < 2; ++mt) {
        int f0 = mgroup * 32 + mt * 16 + gr;
        bA[mt] = g_bfused[f0]; bB[mt] = g_bfused[f0 + 8];
    }
    ln_stats(acc, bA, bB, pSum, pSq, meanv, rstdv, mgroup, lane);
    {
        float gA[2], gB[2], eA[2], eB[2];
        #pragma unroll
        for (int mt = 0; mt < 2; ++mt) {
            int f0 = mgroup * 32 + mt * 16 + gr;
            gA[mt] = g1[f0]; gB[mt] = g1[f0 + 8];
            eA[mt] = be1[f0]; eB[mt] = be1[f0 + 8];
        }
        #pragma unroll
        for (int nt = 0; nt < 5; ++nt) {
            int nA = nt * 8 + 2 * tig, nB = nA + 1;
            float mA = meanv[nA], mB = meanv[nB];
            float rA = rstdv[nA], rB = rstdv[nB];
            #pragma unroll
            for (int mt = 0; mt < 2; ++mt) {
                int f0 = mgroup * 32 + mt * 16 + gr;
                float x0 = acc[mt][nt][0] + bA[mt];
                float x1 = acc[mt][nt][1] + bA[mt];
                float x2 = acc[mt][nt][2] + bB[mt];
                float x3 = acc[mt][nt][3] + bB[mt];
                h1h[nA * ABS + f0]     = __float2half(gelu_exact(fmaf((x0 - mA) * rA, gA[mt], eA[mt])));
                h1h[nB * ABS + f0]     = __float2half(gelu_exact(fmaf((x1 - mB) * rB, gA[mt], eA[mt])));
                h1h[nA * ABS + f0 + 8] = __float2half(gelu_exact(fmaf((x2 - mA) * rA, gB[mt], eB[mt])));
                h1h[nB * ABS + f0 + 8] = __float2half(gelu_exact(fmaf((x3 - mB) * rB, gB[mt], eB[mt])));
            }
        }
    }
    __syncthreads();

    // ==== agg2 (fp16) -> Xs ====
    agg_h(h1h, nbr, Xs, t);
    __syncthreads();

    // ==== GEMM2 -> LN2 -> residual(h1h) -> gelu -> fused per-graph max -> STG ====
    gemm2(Xs, mgroup, lane, acc);
    #pragma unroll
    for (int mt = 0; mt < 2; ++mt) {
        int f0 = mgroup * 32 + mt * 16 + gr;
        bA[mt] = b2[f0]; bB[mt] = b2[f0 + 8];
    }
    ln_stats(acc, bA, bB, pSum, pSq, meanv, rstdv, mgroup, lane);
    {
        float gA[2], gB[2], eA[2], eB[2];
        #pragma unroll
        for (int mt = 0; mt < 2; ++mt) {
            int f0 = mgroup * 32 + mt * 16 + gr;
            gA[mt] = g2[f0]; gB[mt] = g2[f0 + 8];
            eA[mt] = be2[f0]; eB[mt] = be2[f0 + 8];
        }
        float mx[2][2][2];   // [graph][mt][feature pair]
        #pragma unroll
        for (int gph = 0; gph < 2; ++gph)
            #pragma unroll
            for (int mt = 0; mt < 2; ++mt)
                mx[gph][mt][0] = mx[gph][mt][1] = -3.4e38f;

        #pragma unroll
        for (int nt = 0; nt < 5; ++nt) {
            int nA = nt * 8 + 2 * tig, nB = nA + 1;
            int gph = (nA >= NPG) ? 1 : 0;   // nA,nB same graph (nA even)
            float mA = meanv[nA], mB = meanv[nB];
            float rA = rstdv[nA], rB = rstdv[nB];
            #pragma unroll
            for (int mt = 0; mt < 2; ++mt) {
                int f0 = mgroup * 32 + mt * 16 + gr;
                float x0 = acc[mt][nt][0] + bA[mt];
                float x1 = acc[mt][nt][1] + bA[mt];
                float x2 = acc[mt][nt][2] + bB[mt];
                float x3 = acc[mt][nt][3] + bB[mt];
                float h0 = __half2float(h1h[nA * ABS + f0]);
                float h1v = __half2float(h1h[nB * ABS + f0]);
                float h2 = __half2float(h1h[nA * ABS + f0 + 8]);
                float h3 = __half2float(h1h[nB * ABS + f0 + 8]);
                float v0 = gelu_exact(h0  + fmaf((x0 - mA) * rA, gA[mt], eA[mt]));
                float v1 = gelu_exact(h1v + fmaf((x1 - mB) * rB, gA[mt], eA[mt]));
                float v2 = gelu_exact(h2  + fmaf((x2 - mA) * rA, gB[mt], eB[mt]));
                float v3 = gelu_exact(h3  + fmaf((x3 - mB) * rB, gB[mt], eB[mt]));
                mx[gph][mt][0] = fmaxf(mx[gph][mt][0], fmaxf(v0, v1));
                mx[gph][mt][1] = fmaxf(mx[gph][mt][1], fmaxf(v2, v3));
            }
        }
        // combine across tig lanes (same gr, same features)
        #pragma unroll
        for (int gph = 0; gph < 2; ++gph)
            #pragma unroll
            for (int mt = 0; mt < 2; ++mt)
                #pragma unroll
                for (int p = 0; p < 2; ++p) {
                    float v = mx[gph][mt][p];
                    v = fmaxf(v, __shfl_xor_sync(0xffffffffu, v, 1));
                    v = fmaxf(v, __shfl_xor_sync(0xffffffffu, v, 2));
                    mx[gph][mt][p] = v;
                }
        if (tig == 0) {
            float* og = out + (size_t)blockIdx.x * (G * HID);
            #pragma unroll
            for (int gph = 0; gph < 2; ++gph)
                #pragma unroll
                for (int mt = 0; mt < 2; ++mt) {
                    int f0 = mgroup * 32 + mt * 16 + gr;
                    og[gph * HID + f0]     = mx[gph][mt][0];
                    og[gph * HID + f0 + 8] = mx[gph][mt][1];
                }
        }
    }
}

extern "C" void kernel_launch(void* const* d_in, const int* in_sizes, int n_in,
                              void* d_out, int out_size) {
    const float* x_all   = (const float*)d_in[0];
    const float* w_embed = (const float*)d_in[1];
    const float* b_embed = (const float*)d_in[2];
    const float* w1      = (const float*)d_in[3];
    const float* b1      = (const float*)d_in[4];
    const float* w2      = (const float*)d_in[5];
    const float* b2      = (const float*)d_in[6];
    const float* g1      = (const float*)d_in[7];
    const float* be1     = (const float*)d_in[8];
    const float* g2      = (const float*)d_in[9];
    const float* be2     = (const float*)d_in[10];
    float* out = (float*)d_out;

    const int B = in_sizes[0] / (NPG * INDIM);

    static int attr_set = 0;
    if (!attr_set) {
        cudaFuncSetAttribute(hbond_gnn_mma,
                             cudaFuncAttributeMaxDynamicSharedMemorySize, SMEM_BYTES);
        attr_set = 1;
    }

    prep_fuse<<<1, 128>>>(w_embed, b_embed, w1, b1);
    prep_wfrag1<<<1, 256>>>();
    prep_wfrag2<<<8, 256>>>(w2);
    hbond_gnn_mma<<<B / G, 128, SMEM_BYTES>>>(x_all, g1, be1, b2, g2, be2, out);
}

// round 16
// speedup vs baseline: 1.0918x; 1.0918x over previous
#include <cuda_runtime.h>
#include <cuda_fp16.h>
#include <math.h>

#define G      2          // graphs per block
#define NODES  40         // G*20
#define NPG    20
#define HID    128
#define INDIM  9
#define KNN    5
#define ABS    136        // fp16 plane stride (halfs)
#define XAS    40         // fp16 xagg stride (halfs)

typedef unsigned int u32;

__device__ float g_bfused[HID];

// mma A-operand fragments, fp16 hi/lo planes.
__device__ u32 g_Wf1Hi[1024];
__device__ u32 g_Wf1Lo[1024];
__device__ u32 g_Wf2Hi[8192];
__device__ u32 g_Wf2Lo[8192];

// Single prep kernel: blocks 0-7 build W2 fragments; block 8 builds fused
// layer-1 weight (We@W1) in smem, bfused, and its fragments.
__global__ void prep_all(const float* __restrict__ w_embed,
                         const float* __restrict__ b_embed,
                         const float* __restrict__ w1,
                         const float* __restrict__ b1,
                         const float* __restrict__ w2) {
    if (blockIdx.x < 8) {
        int t = blockIdx.x * 256 + threadIdx.x;    // 0..2047
        int mt = t >> 8, kt = (t >> 5) & 7, l = t & 31;
        int gr = l >> 2, tig = l & 3;
        int base = ((mt * 8 + kt) * 32 + l) * 4;
        #pragma unroll
        for (int r = 0; r < 4; ++r) {
            int row = gr + ((r & 1) ? 8 : 0);
            int kb  = tig * 2 + ((r >= 2) ? 8 : 0);
            int m = mt * 16 + row, k = kt * 16 + kb;
            float v0 = w2[k * HID + m], v1 = w2[(k + 1) * HID + m];
            __half h0 = __float2half(v0), h1 = __float2half(v1);
            float l0 = v0 - __half2float(h0), l1 = v1 - __half2float(h1);
            __half2 hi; hi.x = h0; hi.y = h1;
            __half2 lo; lo.x = __float2half(l0); lo.y = __float2half(l1);
            g_Wf2Hi[base + r] = *(u32*)&hi;
            g_Wf2Lo[base + r] = *(u32*)&lo;
        }
        return;
    }
    // block 8: Wfused = We@W1 (9x128) in smem, bfused, then layer-1 fragments.
    __shared__ float WfS[INDIM * HID];
    int t = threadIdx.x;
    for (int idx = t; idx < INDIM * HID; idx += 256) {
        int j = idx / HID, c = idx % HID;
        float s = 0.0f;
        for (int k = 0; k < HID; ++k)
            s = fmaf(w_embed[j * HID + k], w1[k * HID + c], s);
        WfS[idx] = s;
    }
    if (t < HID) {
        float sb = 0.0f;
        for (int k = 0; k < HID; ++k)
            sb = fmaf(b_embed[k], w1[k * HID + t], sb);
        g_bfused[t] = 5.0f * sb + b1[t];
    }
    __syncthreads();
    {
        int mt = t >> 5, l = t & 31;
        int gr = l >> 2, tig = l & 3;
        if (t < 256) {
            int base = (mt * 32 + l) * 4;
            #pragma unroll
            for (int r = 0; r < 4; ++r) {
                int row = gr + ((r & 1) ? 8 : 0);
                int kb  = tig * 2 + ((r >= 2) ? 8 : 0);
                int m = mt * 16 + row, k = kb;
                float v0 = (k     < INDIM) ? WfS[k * HID + m]       : 0.0f;
                float v1 = (k + 1 < INDIM) ? WfS[(k + 1) * HID + m] : 0.0f;
                __half h0 = __float2half(v0), h1 = __float2half(v1);
                float l0 = v0 - __half2float(h0), l1 = v1 - __half2float(h1);
                __half2 hi; hi.x = h0; hi.y = h1;
                __half2 lo; lo.x = __float2half(l0); lo.y = __float2half(l1);
                g_Wf1Hi[base + r] = *(u32*)&hi;
                g_Wf1Lo[base + r] = *(u32*)&lo;
            }
        }
    }
}

__device__ __forceinline__ float gelu_exact(float x) {
    return 0.5f * x * (1.0f + erff(x * 0.70710678118654752440f));
}

#define MMA(d, a, b0v, b1v)                                                       \
    asm volatile("mma.sync.aligned.m16n8k16.row.col.f32.f16.f16.f32 "              \
                 "{%0,%1,%2,%3},{%4,%5,%6,%7},{%8,%9},{%0,%1,%2,%3};"              \
                 : "+f"(d[0]), "+f"(d[1]), "+f"(d[2]), "+f"(d[3])                  \
                 : "r"(a[0]), "r"(a[1]), "r"(a[2]), "r"(a[3]), "r"(b0v), "r"(b1v))

// Layer-1 fused GEMM: K=16 (9 real), X = xagg hi/lo planes, 3 mma terms.
__device__ __forceinline__ void gemm1p(const __half* __restrict__ XsHi,
                                       const __half* __restrict__ XsLo,
                                       int mgroup, int lane,
                                       float acc[2][5][4]) {
    const int gr = lane >> 2, tig = lane & 3;
    u32 ah[2][4], al[2][4];
    #pragma unroll
    for (int mt = 0; mt < 2; ++mt) {
        int idx = ((mgroup * 2 + mt) * 32 + lane) * 4;
        uint4 h = *(const uint4*)&g_Wf1Hi[idx];
        ah[mt][0] = h.x; ah[mt][1] = h.y; ah[mt][2] = h.z; ah[mt][3] = h.w;
        uint4 lo = *(const uint4*)&g_Wf1Lo[idx];
        al[mt][0] = lo.x; al[mt][1] = lo.y; al[mt][2] = lo.z; al[mt][3] = lo.w;
    }
    #pragma unroll
    for (int mt = 0; mt < 2; ++mt)
        #pragma unroll
        for (int nt = 0; nt < 5; ++nt)
            #pragma unroll
            for (int r = 0; r < 4; ++r) acc[mt][nt][r] = 0.0f;
    #pragma unroll
    for (int nt = 0; nt < 5; ++nt) {
        int n0 = nt * 8 + gr;
        u32 bh0 = *(const u32*)(XsHi + n0 * XAS + 2 * tig);
        u32 bh1 = *(const u32*)(XsHi + n0 * XAS + 2 * tig + 8);
        u32 bl0 = *(const u32*)(XsLo + n0 * XAS + 2 * tig);
        u32 bl1 = *(const u32*)(XsLo + n0 * XAS + 2 * tig + 8);
        #pragma unroll
        for (int mt = 0; mt < 2; ++mt) {
            MMA(acc[mt][nt], ah[mt], bh0, bh1);
            MMA(acc[mt][nt], al[mt], bh0, bh1);
            MMA(acc[mt][nt], ah[mt], bl0, bl1);
        }
    }
}

// Layer-2 GEMM: W2 = Wh+Wl fp16 planes vs single fp16 activation plane.
__device__ __forceinline__ void gemm2(const __half* __restrict__ Xs,
                                      int mgroup, int lane,
                                      float acc[2][5][4]) {
    const int gr = lane >> 2, tig = lane & 3;
    #pragma unroll
    for (int mt = 0; mt < 2; ++mt)
        #pragma unroll
        for (int nt = 0; nt < 5; ++nt)
            #pragma unroll
            for (int r = 0; r < 4; ++r) acc[mt][nt][r] = 0.0f;
    #pragma unroll
    for (int kt = 0; kt < 8; ++kt) {
        u32 ah[2][4], al[2][4];
        #pragma unroll
        for (int mt = 0; mt < 2; ++mt) {
            int idx = (((mgroup * 2 + mt) * 8 + kt) * 32 + lane) * 4;
            uint4 h = *(const uint4*)&g_Wf2Hi[idx];
            ah[mt][0] = h.x; ah[mt][1] = h.y; ah[mt][2] = h.z; ah[mt][3] = h.w;
            uint4 lo = *(const uint4*)&g_Wf2Lo[idx];
            al[mt][0] = lo.x; al[mt][1] = lo.y; al[mt][2] = lo.z; al[mt][3] = lo.w;
        }
        u32 bh[5][2];
        const int kb = kt * 16 + 2 * tig;
        #pragma unroll
        for (int nt = 0; nt < 5; ++nt) {
            int n0 = nt * 8 + gr;
            bh[nt][0] = *(const u32*)(Xs + n0 * ABS + kb);
            bh[nt][1] = *(const u32*)(Xs + n0 * ABS + kb + 8);
        }
        #pragma unroll
        for (int mt = 0; mt < 2; ++mt)
            #pragma unroll
            for (int nt = 0; nt < 5; ++nt) {
                MMA(acc[mt][nt], ah[mt], bh[nt][0], bh[nt][1]);
                MMA(acc[mt][nt], al[mt], bh[nt][0], bh[nt][1]);
            }
    }
}

// Shared LN stats: partials -> smem -> combine. All 128 threads participate.
__device__ __forceinline__ void ln_stats(float acc[2][5][4],
                                         const float bA[2], const float bB[2],
                                         float* pSum, float* pSq,
                                         float* meanv, float* rstdv,
                                         int mgroup, int lane) {
    const int gr = lane >> 2, tig = lane & 3;
    #pragma unroll
    for (int nt = 0; nt < 5; ++nt) {
        float sA = 0, sB = 0, qA = 0, qB = 0;
        #pragma unroll
        for (int mt = 0; mt < 2; ++mt) {
            float x0 = acc[mt][nt][0] + bA[mt];
            float x1 = acc[mt][nt][1] + bA[mt];
            float x2 = acc[mt][nt][2] + bB[mt];
            float x3 = acc[mt][nt][3] + bB[mt];
            sA += x0 + x2; sB += x1 + x3;
            qA += x0 * x0 + x2 * x2; qB += x1 * x1 + x3 * x3;
        }
        #pragma unroll
        for (int off = 4; off <= 16; off <<= 1) {
            sA += __shfl_xor_sync(0xffffffffu, sA, off);
            sB += __shfl_xor_sync(0xffffffffu, sB, off);
            qA += __shfl_xor_sync(0xffffffffu, qA, off);
            qB += __shfl_xor_sync(0xffffffffu, qB, off);
        }
        if (gr == 0) {
            int nA = nt * 8 + 2 * tig;
            pSum[mgroup * NODES + nA]     = sA;
            pSum[mgroup * NODES + nA + 1] = sB;
            pSq [mgroup * NODES + nA]     = qA;
            pSq [mgroup * NODES + nA + 1] = qB;
        }
    }
    __syncthreads();
    if (threadIdx.x < NODES) {
        int n = threadIdx.x;
        float S = pSum[n] + pSum[NODES + n] + pSum[2 * NODES + n] + pSum[3 * NODES + n];
        float Q = pSq[n]  + pSq[NODES + n]  + pSq[2 * NODES + n]  + pSq[3 * NODES + n];
        float m = S * (1.0f / 128.0f);
        float var = fmaxf(Q * (1.0f / 128.0f) - m * m, 0.0f);
        meanv[n] = m;
        rstdv[n] = rsqrtf(var + 1e-5f);
    }
    __syncthreads();
}

// agg over knn from fp16 h1h plane (LDS.128, HADD2), write fp16 Xs plane.
__device__ __forceinline__ void agg_h(const __half* __restrict__ h1h,
                                      const int* __restrict__ nbr,
                                      __half* __restrict__ Xs, int t) {
    #pragma unroll
    for (int i = 0; i < 5; ++i) {
        int q = t + 128 * i;              // 640 chunks of 8 halfs
        int n = q >> 4;
        int f8 = (q & 15) * 8;
        const int* nb = &nbr[n * KNN];
        uint4 a0 = *(const uint4*)(h1h + nb[0] * ABS + f8);
        __half2 s0 = *(__half2*)&a0.x, s1 = *(__half2*)&a0.y;
        __half2 s2 = *(__half2*)&a0.z, s3 = *(__half2*)&a0.w;
        #pragma unroll
        for (int r = 1; r < KNN; ++r) {
            uint4 a = *(const uint4*)(h1h + nb[r] * ABS + f8);
            s0 = __hadd2(s0, *(__half2*)&a.x);
            s1 = __hadd2(s1, *(__half2*)&a.y);
            s2 = __hadd2(s2, *(__half2*)&a.z);
            s3 = __hadd2(s3, *(__half2*)&a.w);
        }
        uint4 o;
        o.x = *(u32*)&s0; o.y = *(u32*)&s1; o.z = *(u32*)&s2; o.w = *(u32*)&s3;
        *(uint4*)(Xs + n * ABS + f8) = o;
    }
}

#define SMEM_BYTES 24160

__global__ __launch_bounds__(128, 5)
void hbond_gnn_mma(const float* __restrict__ x_all,
                   const float* __restrict__ g1,
                   const float* __restrict__ be1,
                   const float* __restrict__ b2,
                   const float* __restrict__ g2,
                   const float* __restrict__ be2,
                   float* __restrict__ out) {
    extern __shared__ char smem[];
    // Lifetimes: xs (load..xagg) aliases Xs (agg2..gemm2).
    //            XsHi/XsLo (xagg..gemm1p) alias h1h (epilogue1..end).
    __half* Xs   = (__half*)smem;                       // 40*136*2 = 10880
    float*  xs   = (float*)smem;                        // 360*4 = 1440 (alias)
    __half* h1h  = (__half*)(smem + 10880);             // 10880
    __half* XsHi = (__half*)(smem + 10880);             // 3200 (alias)
    __half* XsLo = (__half*)(smem + 14080);             // 3200 (alias)
    int*   nbr   = (int*)(smem + 21760);                // 200*4 = 800
    float* pSum  = (float*)(smem + 22560);              // 640
    float* pSq   = (float*)(smem + 23200);              // 640
    float* meanv = (float*)(smem + 23840);              // 160
    float* rstdv = (float*)(smem + 24000);              // 160

    const int t = threadIdx.x;
    const int lane = t & 31;
    const int mgroup = t >> 5;                           // warp = m-group (0..3)
    const int gr = lane >> 2, tig = lane & 3;
    const float* x = x_all + (size_t)blockIdx.x * (NODES * INDIM);

    // ---- node features ----
    for (int i = t; i < NODES * INDIM; i += 128) xs[i] = x[i];
    __syncthreads();

    // ---- KNN (d2 in registers; ties -> lower index) + exact fp32 xagg ----
    if (t < NODES) {
        const int gb = (t / NPG) * NPG;
        const float* pi = &xs[t * INDIM + 6];
        const float px = pi[0], py = pi[1], pz = pi[2];
        float d2r[NPG];
        #pragma unroll
        for (int j = 0; j < NPG; ++j) {
            const float* pj = &xs[(gb + j) * INDIM + 6];
            float dx = px - pj[0], dy = py - pj[1], dz = pz - pj[2];
            d2r[j] = fmaf(dx, dx, fmaf(dy, dy, dz * dz));
        }
        unsigned mask = 0;
        int nb[KNN];
        #pragma unroll
        for (int r = 0; r < KNN; ++r) {
            float best = 3.4e38f; int bj = 0;
            #pragma unroll
            for (int j = 0; j < NPG; ++j) {
                if (!((mask >> j) & 1u) && d2r[j] < best) { best = d2r[j]; bj = j; }
            }
            mask |= 1u << bj;
            nb[r] = gb + bj;
            nbr[t * KNN + r] = nb[r];
        }
        __half* hi = XsHi + t * XAS;
        __half* lo = XsLo + t * XAS;
        #pragma unroll
        for (int j = 0; j < INDIM; ++j) {
            float s = 0.0f;
            #pragma unroll
            for (int r = 0; r < KNN; ++r) s += xs[nb[r] * INDIM + j];
            __half h = __float2half(s);
            hi[j] = h;
            lo[j] = __float2half(s - __half2float(h));
        }
        const __half z = __float2half(0.0f);
        #pragma unroll
        for (int j = INDIM; j < 16; ++j) { hi[j] = z; lo[j] = z; }
    }
    __syncthreads();

    float acc[2][5][4];
    float bA[2], bB[2];

    // ==== fused layer 1: (adj@x)@(We@W1) + bfused -> LN1 -> gelu -> h1h (fp16) ====
    gemm1p(XsHi, XsLo, mgroup, lane, acc);
    #pragma unroll
    for (int mt = 0; mt < 2; ++mt) {
        int f0 = mgroup * 32 + mt * 16 + gr;
        bA[mt] = g_bfused[f0]; bB[mt] = g_bfused[f0 + 8];
    }
    ln_stats(acc, bA, bB, pSum, pSq, meanv, rstdv, mgroup, lane);
    {
        float gA[2], gB[2], eA[2], eB[2];
        #pragma unroll
        for (int mt = 0; mt < 2; ++mt) {
            int f0 = mgroup * 32 + mt * 16 + gr;
            gA[mt] = g1[f0]; gB[mt] = g1[f0 + 8];
            eA[mt] = be1[f0]; eB[mt] = be1[f0 + 8];
        }
        #pragma unroll
        for (int nt = 0; nt < 5; ++nt) {
            int nA = nt * 8 + 2 * tig, nB = nA + 1;
            float mA = meanv[nA], mB = meanv[nB];
            float rA = rstdv[nA], rB = rstdv[nB];
            #pragma unroll
            for (int mt = 0; mt < 2; ++mt) {
                int f0 = mgroup * 32 + mt * 16 + gr;
                float x0 = acc[mt][nt][0] + bA[mt];
                float x1 = acc[mt][nt][1] + bA[mt];
                float x2 = acc[mt][nt][2] + bB[mt];
                float x3 = acc[mt][nt][3] + bB[mt];
                h1h[nA * ABS + f0]     = __float2half(gelu_exact(fmaf((x0 - mA) * rA, gA[mt], eA[mt])));
                h1h[nB * ABS + f0]     = __float2half(gelu_exact(fmaf((x1 - mB) * rB, gA[mt], eA[mt])));
                h1h[nA * ABS + f0 + 8] = __float2half(gelu_exact(fmaf((x2 - mA) * rA, gB[mt], eB[mt])));
                h1h[nB * ABS + f0 + 8] = __float2half(gelu_exact(fmaf((x3 - mB) * rB, gB[mt], eB[mt])));
            }
        }
    }
    __syncthreads();

    // ==== agg2 (fp16) -> Xs ====
    agg_h(h1h, nbr, Xs, t);
    __syncthreads();

    // ==== GEMM2 -> LN2 -> residual(h1h) -> gelu -> fused per-graph max -> STG ====
    gemm2(Xs, mgroup, lane, acc);
    #pragma unroll
    for (int mt = 0; mt < 2; ++mt) {
        int f0 = mgroup * 32 + mt * 16 + gr;
        bA[mt] = b2[f0]; bB[mt] = b2[f0 + 8];
    }
    ln_stats(acc, bA, bB, pSum, pSq, meanv, rstdv, mgroup, lane);
    {
        float gA[2], gB[2], eA[2], eB[2];
        #pragma unroll
        for (int mt = 0; mt < 2; ++mt) {
            int f0 = mgroup * 32 + mt * 16 + gr;
            gA[mt] = g2[f0]; gB[mt] = g2[f0 + 8];
            eA[mt] = be2[f0]; eB[mt] = be2[f0 + 8];
        }
        float mx[2][2][2];   // [graph][mt][feature pair]
        #pragma unroll
        for (int gph = 0; gph < 2; ++gph)
            #pragma unroll
            for (int mt = 0; mt < 2; ++mt)
                mx[gph][mt][0] = mx[gph][mt][1] = -3.4e38f;

        #pragma unroll
        for (int nt = 0; nt < 5; ++nt) {
            int nA = nt * 8 + 2 * tig, nB = nA + 1;
            int gph = (nA >= NPG) ? 1 : 0;   // nA,nB same graph (nA even)
            float mA = meanv[nA], mB = meanv[nB];
            float rA = rstdv[nA], rB = rstdv[nB];
            #pragma unroll
            for (int mt = 0; mt < 2; ++mt) {
                int f0 = mgroup * 32 + mt * 16 + gr;
                float x0 = acc[mt][nt][0] + bA[mt];
                float x1 = acc[mt][nt][1] + bA[mt];
                float x2 = acc[mt][nt][2] + bB[mt];
                float x3 = acc[mt][nt][3] + bB[mt];
                float h0 = __half2float(h1h[nA * ABS + f0]);
                float h1v = __half2float(h1h[nB * ABS + f0]);
                float h2 = __half2float(h1h[nA * ABS + f0 + 8]);
                float h3 = __half2float(h1h[nB * ABS + f0 + 8]);
                float v0 = gelu_exact(h0  + fmaf((x0 - mA) * rA, gA[mt], eA[mt]));
                float v1 = gelu_exact(h1v + fmaf((x1 - mB) * rB, gA[mt], eA[mt]));
                float v2 = gelu_exact(h2  + fmaf((x2 - mA) * rA, gB[mt], eB[mt]));
                float v3 = gelu_exact(h3  + fmaf((x3 - mB) * rB, gB[mt], eB[mt]));
                mx[gph][mt][0] = fmaxf(mx[gph][mt][0], fmaxf(v0, v1));
                mx[gph][mt][1] = fmaxf(mx[gph][mt][1], fmaxf(v2, v3));
            }
        }
        // combine across tig lanes (same gr, same features)
        #pragma unroll
        for (int gph = 0; gph < 2; ++gph)
            #pragma unroll
            for (int mt = 0; mt < 2; ++mt)
                #pragma unroll
                for (int p = 0; p < 2; ++p) {
                    float v = mx[gph][mt][p];
                    v = fmaxf(v, __shfl_xor_sync(0xffffffffu, v, 1));
                    v = fmaxf(v, __shfl_xor_sync(0xffffffffu, v, 2));
                    mx[gph][mt][p] = v;
                }
        if (tig == 0) {
            float* og = out + (size_t)blockIdx.x * (G * HID);
            #pragma unroll
            for (int gph = 0; gph < 2; ++gph)
                #pragma unroll
                for (int mt = 0; mt < 2; ++mt) {
                    int f0 = mgroup * 32 + mt * 16 + gr;
                    og[gph * HID + f0]     = mx[gph][mt][0];
                    og[gph * HID + f0 + 8] = mx[gph][mt][1];
                }
        }
    }
}

extern "C" void kernel_launch(void* const* d_in, const int* in_sizes, int n_in,
                              void* d_out, int out_size) {
    const float* x_all   = (const float*)d_in[0];
    const float* w_embed = (const float*)d_in[1];
    const float* b_embed = (const float*)d_in[2];
    const float* w1      = (const float*)d_in[3];
    const float* b1      = (const float*)d_in[4];
    const float* w2      = (const float*)d_in[5];
    const float* b2      = (const float*)d_in[6];
    const float* g1      = (const float*)d_in[7];
    const float* be1     = (const float*)d_in[8];
    const float* g2      = (const float*)d_in[9];
    const float* be2     = (const float*)d_in[10];
    float* out = (float*)d_out;

    const int B = in_sizes[0] / (NPG * INDIM);

    static int attr_set = 0;
    if (!attr_set) {
        cudaFuncSetAttribute(hbond_gnn_mma,
                             cudaFuncAttributeMaxDynamicSharedMemorySize, SMEM_BYTES);
        attr_set = 1;
    }

    prep_all<<<9, 256>>>(w_embed, b_embed, w1, b1, w2);
    hbond_gnn_mma<<<B / G, 128, SMEM_BYTES>>>(x_all, g1, be1, b2, g2, be2, out);
}

// round 17
// speedup vs baseline: 1.2082x; 1.1066x over previous
#include <cuda_runtime.h>
#include <cuda_fp16.h>
#include <math.h>

#define G      2          // graphs per block
#define NODES  40         // G*20
#define NPG    20
#define HID    128
#define INDIM  9
#define KNN    5
#define ABS    136        // fp16 plane stride (halfs)
#define XAS    40         // fp16 xagg stride (halfs)

typedef unsigned int u32;

__device__ float g_bfused[HID];

// mma A-operand fragments, fp16 hi/lo planes.
__device__ u32 g_Wf1Hi[1024];
__device__ u32 g_Wf1Lo[1024];
__device__ u32 g_Wf2Hi[8192];
__device__ u32 g_Wf2Lo[8192];

// Single prep kernel: blocks 0-7 build W2 fragments; block 8 builds fused
// layer-1 weight (We@W1) in smem, bfused, and its fragments.
__global__ void prep_all(const float* __restrict__ w_embed,
                         const float* __restrict__ b_embed,
                         const float* __restrict__ w1,
                         const float* __restrict__ b1,
                         const float* __restrict__ w2) {
    if (blockIdx.x < 8) {
        int t = blockIdx.x * 256 + threadIdx.x;    // 0..2047
        int mt = t >> 8, kt = (t >> 5) & 7, l = t & 31;
        int gr = l >> 2, tig = l & 3;
        int base = ((mt * 8 + kt) * 32 + l) * 4;
        #pragma unroll
        for (int r = 0; r < 4; ++r) {
            int row = gr + ((r & 1) ? 8 : 0);
            int kb  = tig * 2 + ((r >= 2) ? 8 : 0);
            int m = mt * 16 + row, k = kt * 16 + kb;
            float v0 = w2[k * HID + m], v1 = w2[(k + 1) * HID + m];
            __half h0 = __float2half(v0), h1 = __float2half(v1);
            float l0 = v0 - __half2float(h0), l1 = v1 - __half2float(h1);
            __half2 hi; hi.x = h0; hi.y = h1;
            __half2 lo; lo.x = __float2half(l0); lo.y = __float2half(l1);
            g_Wf2Hi[base + r] = *(u32*)&hi;
            g_Wf2Lo[base + r] = *(u32*)&lo;
        }
        return;
    }
    // block 8: Wfused = We@W1 (9x128) in smem, bfused, then layer-1 fragments.
    __shared__ float WfS[INDIM * HID];
    int t = threadIdx.x;
    for (int idx = t; idx < INDIM * HID; idx += 256) {
        int j = idx / HID, c = idx % HID;
        float s = 0.0f;
        for (int k = 0; k < HID; ++k)
            s = fmaf(w_embed[j * HID + k], w1[k * HID + c], s);
        WfS[idx] = s;
    }
    if (t < HID) {
        float sb = 0.0f;
        for (int k = 0; k < HID; ++k)
            sb = fmaf(b_embed[k], w1[k * HID + t], sb);
        g_bfused[t] = 5.0f * sb + b1[t];
    }
    __syncthreads();
    {
        int mt = t >> 5, l = t & 31;
        int gr = l >> 2, tig = l & 3;
        if (t < 256) {
            int base = (mt * 32 + l) * 4;
            #pragma unroll
            for (int r = 0; r < 4; ++r) {
                int row = gr + ((r & 1) ? 8 : 0);
                int kb  = tig * 2 + ((r >= 2) ? 8 : 0);
                int m = mt * 16 + row, k = kb;
                float v0 = (k     < INDIM) ? WfS[k * HID + m]       : 0.0f;
                float v1 = (k + 1 < INDIM) ? WfS[(k + 1) * HID + m] : 0.0f;
                __half h0 = __float2half(v0), h1 = __float2half(v1);
                float l0 = v0 - __half2float(h0), l1 = v1 - __half2float(h1);
                __half2 hi; hi.x = h0; hi.y = h1;
                __half2 lo; lo.x = __float2half(l0); lo.y = __float2half(l1);
                g_Wf1Hi[base + r] = *(u32*)&hi;
                g_Wf1Lo[base + r] = *(u32*)&lo;
            }
        }
    }
}

__device__ __forceinline__ float gelu_exact(float x) {
    return 0.5f * x * (1.0f + erff(x * 0.70710678118654752440f));
}

#define MMA(d, a, b0v, b1v)                                                       \
    asm volatile("mma.sync.aligned.m16n8k16.row.col.f32.f16.f16.f32 "              \
                 "{%0,%1,%2,%3},{%4,%5,%6,%7},{%8,%9},{%0,%1,%2,%3};"              \
                 : "+f"(d[0]), "+f"(d[1]), "+f"(d[2]), "+f"(d[3])                  \
                 : "r"(a[0]), "r"(a[1]), "r"(a[2]), "r"(a[3]), "r"(b0v), "r"(b1v))

// Layer-1 fused GEMM: K=16 (9 real), X = xagg hi/lo planes, 3 mma terms.
__device__ __forceinline__ void gemm1p(const __half* __restrict__ XsHi,
                                       const __half* __restrict__ XsLo,
                                       int mgroup, int lane,
                                       float acc[2][5][4]) {
    const int gr = lane >> 2, tig = lane & 3;
    u32 ah[2][4], al[2][4];
    #pragma unroll
    for (int mt = 0; mt < 2; ++mt) {
        int idx = ((mgroup * 2 + mt) * 32 + lane) * 4;
        uint4 h = *(const uint4*)&g_Wf1Hi[idx];
        ah[mt][0] = h.x; ah[mt][1] = h.y; ah[mt][2] = h.z; ah[mt][3] = h.w;
        uint4 lo = *(const uint4*)&g_Wf1Lo[idx];
        al[mt][0] = lo.x; al[mt][1] = lo.y; al[mt][2] = lo.z; al[mt][3] = lo.w;
    }
    #pragma unroll
    for (int mt = 0; mt < 2; ++mt)
        #pragma unroll
        for (int nt = 0; nt < 5; ++nt)
            #pragma unroll
            for (int r = 0; r < 4; ++r) acc[mt][nt][r] = 0.0f;
    #pragma unroll
    for (int nt = 0; nt < 5; ++nt) {
        int n0 = nt * 8 + gr;
        u32 bh0 = *(const u32*)(XsHi + n0 * XAS + 2 * tig);
        u32 bh1 = *(const u32*)(XsHi + n0 * XAS + 2 * tig + 8);
        u32 bl0 = *(const u32*)(XsLo + n0 * XAS + 2 * tig);
        u32 bl1 = *(const u32*)(XsLo + n0 * XAS + 2 * tig + 8);
        #pragma unroll
        for (int mt = 0; mt < 2; ++mt) {
            MMA(acc[mt][nt], ah[mt], bh0, bh1);
            MMA(acc[mt][nt], al[mt], bh0, bh1);
            MMA(acc[mt][nt], ah[mt], bl0, bl1);
        }
    }
}

// Layer-2 GEMM: W2 = Wh+Wl fp16 planes vs single fp16 activation plane.
__device__ __forceinline__ void gemm2(const __half* __restrict__ Xs,
                                      int mgroup, int lane,
                                      float acc[2][5][4]) {
    const int gr = lane >> 2, tig = lane & 3;
    #pragma unroll
    for (int mt = 0; mt < 2; ++mt)
        #pragma unroll
        for (int nt = 0; nt < 5; ++nt)
            #pragma unroll
            for (int r = 0; r < 4; ++r) acc[mt][nt][r] = 0.0f;
    #pragma unroll
    for (int kt = 0; kt < 8; ++kt) {
        u32 ah[2][4], al[2][4];
        #pragma unroll
        for (int mt = 0; mt < 2; ++mt) {
            int idx = (((mgroup * 2 + mt) * 8 + kt) * 32 + lane) * 4;
            uint4 h = *(const uint4*)&g_Wf2Hi[idx];
            ah[mt][0] = h.x; ah[mt][1] = h.y; ah[mt][2] = h.z; ah[mt][3] = h.w;
            uint4 lo = *(const uint4*)&g_Wf2Lo[idx];
            al[mt][0] = lo.x; al[mt][1] = lo.y; al[mt][2] = lo.z; al[mt][3] = lo.w;
        }
        u32 bh[5][2];
        const int kb = kt * 16 + 2 * tig;
        #pragma unroll
        for (int nt = 0; nt < 5; ++nt) {
            int n0 = nt * 8 + gr;
            bh[nt][0] = *(const u32*)(Xs + n0 * ABS + kb);
            bh[nt][1] = *(const u32*)(Xs + n0 * ABS + kb + 8);
        }
        #pragma unroll
        for (int mt = 0; mt < 2; ++mt)
            #pragma unroll
            for (int nt = 0; nt < 5; ++nt) {
                MMA(acc[mt][nt], ah[mt], bh[nt][0], bh[nt][1]);
                MMA(acc[mt][nt], al[mt], bh[nt][0], bh[nt][1]);
            }
    }
}

// Shared LN stats: partials -> smem -> combine. All 128 threads participate.
__device__ __forceinline__ void ln_stats(float acc[2][5][4],
                                         const float bA[2], const float bB[2],
                                         float* pSum, float* pSq,
                                         float* meanv, float* rstdv,
                                         int mgroup, int lane) {
    const int gr = lane >> 2, tig = lane & 3;
    #pragma unroll
    for (int nt = 0; nt < 5; ++nt) {
        float sA = 0, sB = 0, qA = 0, qB = 0;
        #pragma unroll
        for (int mt = 0; mt < 2; ++mt) {
            float x0 = acc[mt][nt][0] + bA[mt];
            float x1 = acc[mt][nt][1] + bA[mt];
            float x2 = acc[mt][nt][2] + bB[mt];
            float x3 = acc[mt][nt][3] + bB[mt];
            sA += x0 + x2; sB += x1 + x3;
            qA += x0 * x0 + x2 * x2; qB += x1 * x1 + x3 * x3;
        }
        #pragma unroll
        for (int off = 4; off <= 16; off <<= 1) {
            sA += __shfl_xor_sync(0xffffffffu, sA, off);
            sB += __shfl_xor_sync(0xffffffffu, sB, off);
            qA += __shfl_xor_sync(0xffffffffu, qA, off);
            qB += __shfl_xor_sync(0xffffffffu, qB, off);
        }
        if (gr == 0) {
            int nA = nt * 8 + 2 * tig;
            pSum[mgroup * NODES + nA]     = sA;
            pSum[mgroup * NODES + nA + 1] = sB;
            pSq [mgroup * NODES + nA]     = qA;
            pSq [mgroup * NODES + nA + 1] = qB;
        }
    }
    __syncthreads();
    if (threadIdx.x < NODES) {
        int n = threadIdx.x;
        float S = pSum[n] + pSum[NODES + n] + pSum[2 * NODES + n] + pSum[3 * NODES + n];
        float Q = pSq[n]  + pSq[NODES + n]  + pSq[2 * NODES + n]  + pSq[3 * NODES + n];
        float m = S * (1.0f / 128.0f);
        float var = fmaxf(Q * (1.0f / 128.0f) - m * m, 0.0f);
        meanv[n] = m;
        rstdv[n] = rsqrtf(var + 1e-5f);
    }
    __syncthreads();
}

// agg over knn from fp16 h1h plane (LDS.128, HADD2), write fp16 Xs plane.
__device__ __forceinline__ void agg_h(const __half* __restrict__ h1h,
                                      const int* __restrict__ nbr,
                                      __half* __restrict__ Xs, int t) {
    #pragma unroll
    for (int i = 0; i < 5; ++i) {
        int q = t + 128 * i;              // 640 chunks of 8 halfs
        int n = q >> 4;
        int f8 = (q & 15) * 8;
        const int* nb = &nbr[n * KNN];
        uint4 a0 = *(const uint4*)(h1h + nb[0] * ABS + f8);
        __half2 s0 = *(__half2*)&a0.x, s1 = *(__half2*)&a0.y;
        __half2 s2 = *(__half2*)&a0.z, s3 = *(__half2*)&a0.w;
        #pragma unroll
        for (int r = 1; r < KNN; ++r) {
            uint4 a = *(const uint4*)(h1h + nb[r] * ABS + f8);
            s0 = __hadd2(s0, *(__half2*)&a.x);
            s1 = __hadd2(s1, *(__half2*)&a.y);
            s2 = __hadd2(s2, *(__half2*)&a.z);
            s3 = __hadd2(s3, *(__half2*)&a.w);
        }
        uint4 o;
        o.x = *(u32*)&s0; o.y = *(u32*)&s1; o.z = *(u32*)&s2; o.w = *(u32*)&s3;
        *(uint4*)(Xs + n * ABS + f8) = o;
    }
}

#define SMEM_BYTES 24160

__global__ __launch_bounds__(128, 5)
void hbond_gnn_mma(const float* __restrict__ x_all,
                   const float* __restrict__ g1,
                   const float* __restrict__ be1,
                   const float* __restrict__ b2,
                   const float* __restrict__ g2,
                   const float* __restrict__ be2,
                   float* __restrict__ out) {
    extern __shared__ char smem[];
    // Lifetimes: xs (load..xagg) aliases Xs (agg2..gemm2).
    //            XsHi/XsLo (xagg..gemm1p) alias h1h (epilogue1..end).
    __half* Xs   = (__half*)smem;                       // 40*136*2 = 10880
    float*  xs   = (float*)smem;                        // 360*4 = 1440 (alias)
    __half* h1h  = (__half*)(smem + 10880);             // 10880
    __half* XsHi = (__half*)(smem + 10880);             // 3200 (alias)
    __half* XsLo = (__half*)(smem + 14080);             // 3200 (alias)
    int*   nbr   = (int*)(smem + 21760);                // 200*4 = 800
    float* pSum  = (float*)(smem + 22560);              // 640
    float* pSq   = (float*)(smem + 23200);              // 640
    float* meanv = (float*)(smem + 23840);              // 160
    float* rstdv = (float*)(smem + 24000);              // 160

    const int t = threadIdx.x;
    const int lane = t & 31;
    const int mgroup = t >> 5;                           // warp = m-group (0..3)
    const int gr = lane >> 2, tig = lane & 3;
    const float* x = x_all + (size_t)blockIdx.x * (NODES * INDIM);

    // ---- node features ----
    for (int i = t; i < NODES * INDIM; i += 128) xs[i] = x[i];
    __syncthreads();

    // ---- KNN (d2 in registers; ties -> lower index) + exact fp32 xagg ----
    if (t < NODES) {
        const int gb = (t / NPG) * NPG;
        const float* pi = &xs[t * INDIM + 6];
        const float px = pi[0], py = pi[1], pz = pi[2];
        float d2r[NPG];
        #pragma unroll
        for (int j = 0; j < NPG; ++j) {
            const float* pj = &xs[(gb + j) * INDIM + 6];
            float dx = px - pj[0], dy = py - pj[1], dz = pz - pj[2];
            d2r[j] = fmaf(dx, dx, fmaf(dy, dy, dz * dz));
        }
        unsigned mask = 0;
        int nb[KNN];
        #pragma unroll
        for (int r = 0; r < KNN; ++r) {
            float best = 3.4e38f; int bj = 0;
            #pragma unroll
            for (int j = 0; j < NPG; ++j) {
                if (!((mask >> j) & 1u) && d2r[j] < best) { best = d2r[j]; bj = j; }
            }
            mask |= 1u << bj;
            nb[r] = gb + bj;
            nbr[t * KNN + r] = nb[r];
        }
        __half* hi = XsHi + t * XAS;
        __half* lo = XsLo + t * XAS;
        #pragma unroll
        for (int j = 0; j < INDIM; ++j) {
            float s = 0.0f;
            #pragma unroll
            for (int r = 0; r < KNN; ++r) s += xs[nb[r] * INDIM + j];
            __half h = __float2half(s);
            hi[j] = h;
            lo[j] = __float2half(s - __half2float(h));
        }
        const __half z = __float2half(0.0f);
        #pragma unroll
        for (int j = INDIM; j < 16; ++j) { hi[j] = z; lo[j] = z; }
    }
    __syncthreads();

    float acc[2][5][4];
    float bA[2], bB[2];

    // ==== fused layer 1: (adj@x)@(We@W1) + bfused -> LN1 -> gelu -> h1h (fp16) ====
    gemm1p(XsHi, XsLo, mgroup, lane, acc);
    #pragma unroll
    for (int mt = 0; mt < 2; ++mt) {
        int f0 = mgroup * 32 + mt * 16 + gr;
        bA[mt] = g_bfused[f0]; bB[mt] = g_bfused[f0 + 8];
    }
    ln_stats(acc, bA, bB, pSum, pSq, meanv, rstdv, mgroup, lane);
    {
        float gA[2], gB[2], eA[2], eB[2];
        #pragma unroll
        for (int mt = 0; mt < 2; ++mt) {
            int f0 = mgroup * 32 + mt * 16 + gr;
            gA[mt] = g1[f0]; gB[mt] = g1[f0 + 8];
            eA[mt] = be1[f0]; eB[mt] = be1[f0 + 8];
        }
        #pragma unroll
        for (int nt = 0; nt < 5; ++nt) {
            int nA = nt * 8 + 2 * tig, nB = nA + 1;
            float mA = meanv[nA], mB = meanv[nB];
            float rA = rstdv[nA], rB = rstdv[nB];
            #pragma unroll
            for (int mt = 0; mt < 2; ++mt) {
                int f0 = mgroup * 32 + mt * 16 + gr;
                float x0 = acc[mt][nt][0] + bA[mt];
                float x1 = acc[mt][nt][1] + bA[mt];
                float x2 = acc[mt][nt][2] + bB[mt];
                float x3 = acc[mt][nt][3] + bB[mt];
                h1h[nA * ABS + f0]     = __float2half(gelu_exact(fmaf((x0 - mA) * rA, gA[mt], eA[mt])));
                h1h[nB * ABS + f0]     = __float2half(gelu_exact(fmaf((x1 - mB) * rB, gA[mt], eA[mt])));
                h1h[nA * ABS + f0 + 8] = __float2half(gelu_exact(fmaf((x2 - mA) * rA, gB[mt], eB[mt])));
                h1h[nB * ABS + f0 + 8] = __float2half(gelu_exact(fmaf((x3 - mB) * rB, gB[mt], eB[mt])));
            }
        }
    }
    __syncthreads();

    // ==== agg2 (fp16) -> Xs ====
    agg_h(h1h, nbr, Xs, t);
    __syncthreads();

    // ==== GEMM2 -> LN2 -> residual(h1h) -> per-graph max/min of pre-gelu u ====
    // gelu is unimodal (min at x~-0.751), so max_n gelu(u_n) =
    // max(gelu(max_n u_n), gelu(min_n u_n)) — evaluate gelu on 2 values, not 20.
    gemm2(Xs, mgroup, lane, acc);
    #pragma unroll
    for (int mt = 0; mt < 2; ++mt) {
        int f0 = mgroup * 32 + mt * 16 + gr;
        bA[mt] = b2[f0]; bB[mt] = b2[f0 + 8];
    }
    ln_stats(acc, bA, bB, pSum, pSq, meanv, rstdv, mgroup, lane);
    {
        float gA[2], gB[2], eA[2], eB[2];
        #pragma unroll
        for (int mt = 0; mt < 2; ++mt) {
            int f0 = mgroup * 32 + mt * 16 + gr;
            gA[mt] = g2[f0]; gB[mt] = g2[f0 + 8];
            eA[mt] = be2[f0]; eB[mt] = be2[f0 + 8];
        }
        float umx[2][2][2], umn[2][2][2];   // [graph][mt][feature pair]
        #pragma unroll
        for (int gph = 0; gph < 2; ++gph)
            #pragma unroll
            for (int mt = 0; mt < 2; ++mt) {
                umx[gph][mt][0] = umx[gph][mt][1] = -3.4e38f;
                umn[gph][mt][0] = umn[gph][mt][1] =  3.4e38f;
            }

        #pragma unroll
        for (int nt = 0; nt < 5; ++nt) {
            int nA = nt * 8 + 2 * tig, nB = nA + 1;
            int gph = (nA >= NPG) ? 1 : 0;   // nA,nB same graph (nA even)
            float mA = meanv[nA], mB = meanv[nB];
            float rA = rstdv[nA], rB = rstdv[nB];
            #pragma unroll
            for (int mt = 0; mt < 2; ++mt) {
                int f0 = mgroup * 32 + mt * 16 + gr;
                float x0 = acc[mt][nt][0] + bA[mt];
                float x1 = acc[mt][nt][1] + bA[mt];
                float x2 = acc[mt][nt][2] + bB[mt];
                float x3 = acc[mt][nt][3] + bB[mt];
                float u0 = __half2float(h1h[nA * ABS + f0])     + fmaf((x0 - mA) * rA, gA[mt], eA[mt]);
                float u1 = __half2float(h1h[nB * ABS + f0])     + fmaf((x1 - mB) * rB, gA[mt], eA[mt]);
                float u2 = __half2float(h1h[nA * ABS + f0 + 8]) + fmaf((x2 - mA) * rA, gB[mt], eB[mt]);
                float u3 = __half2float(h1h[nB * ABS + f0 + 8]) + fmaf((x3 - mB) * rB, gB[mt], eB[mt]);
                float p0x = fmaxf(u0, u1), p0n = fminf(u0, u1);
                float p1x = fmaxf(u2, u3), p1n = fminf(u2, u3);
                umx[gph][mt][0] = fmaxf(umx[gph][mt][0], p0x);
                umn[gph][mt][0] = fminf(umn[gph][mt][0], p0n);
                umx[gph][mt][1] = fmaxf(umx[gph][mt][1], p1x);
                umn[gph][mt][1] = fminf(umn[gph][mt][1], p1n);
            }
        }
        // combine across tig lanes (same gr, same features), then gelu on extrema
        #pragma unroll
        for (int gph = 0; gph < 2; ++gph)
            #pragma unroll
            for (int mt = 0; mt < 2; ++mt)
                #pragma unroll
                for (int p = 0; p < 2; ++p) {
                    float vx = umx[gph][mt][p];
                    float vn = umn[gph][mt][p];
                    vx = fmaxf(vx, __shfl_xor_sync(0xffffffffu, vx, 1));
                    vx = fmaxf(vx, __shfl_xor_sync(0xffffffffu, vx, 2));
                    vn = fminf(vn, __shfl_xor_sync(0xffffffffu, vn, 1));
                    vn = fminf(vn, __shfl_xor_sync(0xffffffffu, vn, 2));
                    umx[gph][mt][p] = fmaxf(gelu_exact(vx), gelu_exact(vn));
                }
        if (tig == 0) {
            float* og = out + (size_t)blockIdx.x * (G * HID);
            #pragma unroll
            for (int gph = 0; gph < 2; ++gph)
                #pragma unroll
                for (int mt = 0; mt < 2; ++mt) {
                    int f0 = mgroup * 32 + mt * 16 + gr;
                    og[gph * HID + f0]     = umx[gph][mt][0];
                    og[gph * HID + f0 + 8] = umx[gph][mt][1];
                }
        }
    }
}

extern "C" void kernel_launch(void* const* d_in, const int* in_sizes, int n_in,
                              void* d_out, int out_size) {
    const float* x_all   = (const float*)d_in[0];
    const float* w_embed = (const float*)d_in[1];
    const float* b_embed = (const float*)d_in[2];
    const float* w1      = (const float*)d_in[3];
    const float* b1      = (const float*)d_in[4];
    const float* w2      = (const float*)d_in[5];
    const float* b2      = (const float*)d_in[6];
    const float* g1      = (const float*)d_in[7];
    const float* be1     = (const float*)d_in[8];
    const float* g2      = (const float*)d_in[9];
    const float* be2     = (const float*)d_in[10];
    float* out = (float*)d_out;

    const int B = in_sizes[0] / (NPG * INDIM);

    static int attr_set = 0;
    if (!attr_set) {
        cudaFuncSetAttribute(hbond_gnn_mma,
                             cudaFuncAttributeMaxDynamicSharedMemorySize, SMEM_BYTES);
        attr_set = 1;
    }

    prep_all<<<9, 256>>>(w_embed, b_embed, w1, b1, w2);
    hbond_gnn_mma<<<B / G, 128, SMEM_BYTES>>>(x_all, g1, be1, b2, g2, be2, out);
}